// round 17
// baseline (speedup 1.0000x reference)
#include <cuda_runtime.h>

// Output = 2*PE broadcast over batch: 65536*64*16 fp32 = 256 MB pure stores.
//
// R14-R16: grid oversubscription monotonically raises sustained store
// throughput (1184 CTAs: 4908 GB/s -> 9472: 5501 GB/s; 45.8 -> 41.1 us).
// At 9472 CTAs the libm prologue (expf+sincosf per thread) became ~25% of
// issue. R17: hardcode the 16 channel freqs 10000^(-c/8) and use
// single-MUFU __sinf/__cosf (|err| ~1e-5 << 1e-3 tol), then push to
// 14208 CTAs (~4.7 STG.128/thread).

__device__ __constant__ const float PE_FREQ[16] = {
    1.0000000000e+00f, 3.1622776602e-01f, 1.0000000000e-01f, 3.1622776602e-02f,
    1.0000000000e-02f, 3.1622776602e-03f, 1.0000000000e-03f, 3.1622776602e-04f,
    1.0000000000e-04f, 3.1622776602e-05f, 1.0000000000e-05f, 3.1622776602e-06f,
    1.0000000000e-06f, 3.1622776602e-07f, 1.0000000000e-07f, 3.1622776602e-08f
};

__global__ void __launch_bounds__(256, 8)
pe_broadcast_kernel(float4* __restrict__ out, long long n4) {
    // blockDim.x == 256 and stride is a multiple of 256 float4s, so this
    // thread's (index % 256) is threadIdx.x forever -> compute value once.
    const int t = threadIdx.x;              // float4 index within 1024-float period
    const int pos = t >> 2;                 // sequence position 0..63
    const int c0  = (t & 3) * 4;            // first of 4 consecutive channels

    float4 v;
    {
        float vals[4];
        #pragma unroll
        for (int k = 0; k < 4; ++k) {
            int c = c0 + k;
            float div = (float)pos * PE_FREQ[c];
            // even channel -> sin, odd -> cos; fast MUFU intrinsics
            vals[k] = 2.0f * (((c & 1) == 0) ? __sinf(div) : __cosf(div));
        }
        v.x = vals[0]; v.y = vals[1]; v.z = vals[2]; v.w = vals[3];
    }

    long long idx    = (long long)blockIdx.x * 256 + t;
    const long long stride = (long long)gridDim.x * 256;
    for (; idx < n4; idx += stride) {
        out[idx] = v;
    }
}

extern "C" void kernel_launch(void* const* d_in, const int* in_sizes, int n_in,
                              void* d_out, int out_size) {
    (void)d_in; (void)in_sizes; (void)n_in;
    long long n4 = (long long)out_size / 4;   // 16,777,216 float4
    int blocks = 148 * 96;                    // 14208 CTAs: ~4.7 STG.128/thread
    pe_broadcast_kernel<<<blocks, 256>>>((float4*)d_out, n4);
}